// round 3
// baseline (speedup 1.0000x reference)
#include <cuda_runtime.h>
#include <math.h>
#include <float.h>

#define BB 4
#define TT 2048
#define DD 1024
#define HH 16
#define DH 64
#define M_ROWS (BB*TT)          // 8192
#define N_QKV (3*DD)            // 3072
#define K_DIM DD                // 1024

// -------- scratch (no allocations allowed) --------
__device__ float g_q[BB*HH*TT*DH];    // [b][h][t][d]
__device__ float g_k[BB*HH*TT*DH];
__device__ float g_v[BB*HH*TT*DH];
__device__ float g_att[BB*TT*DD];     // [b][t][h*DH+d]  == rows for out-proj

// ============================================================
// GEMM 128x128x8, 256 threads, 8x8 per thread, fp32
// C = A[M,K] @ W[K,N] + bias ; epilogue variant selected by flag
// ============================================================
__global__ __launch_bounds__(256, 2)
void qkv_gemm_kernel(const float* __restrict__ A, const float* __restrict__ W,
                     const float* __restrict__ bias)
{
    __shared__ float As[8][128];    // k-major transposed A tile
    __shared__ float Bs[8][132];    // padded, rows 16B-aligned (132*4=528)

    const int tid = threadIdx.x;
    const int tx = tid & 15;          // n-group
    const int ty = tid >> 4;          // m-group
    const int n0 = blockIdx.x * 128;
    const int m0 = blockIdx.y * 128;

    float acc[8][8];
#pragma unroll
    for (int i = 0; i < 8; i++)
#pragma unroll
        for (int j = 0; j < 8; j++) acc[i][j] = 0.f;

    // A-tile load mapping: 128 rows x 8 cols = 256 float4
    const int ar = tid >> 1;          // row 0..127
    const int ac4 = (tid & 1) * 4;    // col 0 or 4
    // B-tile load mapping: 8 rows x 128 cols = 256 float4
    const int br = tid >> 5;          // row 0..7
    const int bc = (tid & 31) * 4;    // col

    for (int kt = 0; kt < K_DIM; kt += 8) {
        float4 av = *(const float4*)&A[(size_t)(m0 + ar) * K_DIM + kt + ac4];
        float4 bv = *(const float4*)&W[(size_t)(kt + br) * N_QKV + n0 + bc];
        As[ac4 + 0][ar] = av.x;
        As[ac4 + 1][ar] = av.y;
        As[ac4 + 2][ar] = av.z;
        As[ac4 + 3][ar] = av.w;
        *(float4*)&Bs[br][bc] = bv;
        __syncthreads();
#pragma unroll
        for (int kk = 0; kk < 8; kk++) {
            float4 a0 = *(const float4*)&As[kk][ty * 8];
            float4 a1 = *(const float4*)&As[kk][ty * 8 + 4];
            float4 b0 = *(const float4*)&Bs[kk][tx * 8];
            float4 b1 = *(const float4*)&Bs[kk][tx * 8 + 4];
            float af[8] = {a0.x,a0.y,a0.z,a0.w,a1.x,a1.y,a1.z,a1.w};
            float bf[8] = {b0.x,b0.y,b0.z,b0.w,b1.x,b1.y,b1.z,b1.w};
#pragma unroll
            for (int i = 0; i < 8; i++)
#pragma unroll
                for (int j = 0; j < 8; j++)
                    acc[i][j] = fmaf(af[i], bf[j], acc[i][j]);
        }
        __syncthreads();
    }

    // epilogue: bias + scatter to q/k/v in [b][h][t][d]
#pragma unroll
    for (int i = 0; i < 8; i++) {
        int m = m0 + ty * 8 + i;
        int b = m >> 11;          // /2048
        int t = m & 2047;
#pragma unroll
        for (int j = 0; j < 8; j++) {
            int n = n0 + tx * 8 + j;
            float v = acc[i][j] + bias[n];
            int sec = n >> 10;          // 0=q 1=k 2=v
            int nn = n & 1023;
            int h = nn >> 6;
            int d = nn & 63;
            float* dst = (sec == 0) ? g_q : (sec == 1) ? g_k : g_v;
            dst[((size_t)(b * HH + h) * TT + t) * DH + d] = v;
        }
    }
}

__global__ __launch_bounds__(256, 2)
void out_gemm_kernel(const float* __restrict__ W,
                     const float* __restrict__ bias, float* __restrict__ out)
{
    __shared__ float As[8][128];
    __shared__ float Bs[8][132];

    const int tid = threadIdx.x;
    const int tx = tid & 15;
    const int ty = tid >> 4;
    const int n0 = blockIdx.x * 128;
    const int m0 = blockIdx.y * 128;

    float acc[8][8];
#pragma unroll
    for (int i = 0; i < 8; i++)
#pragma unroll
        for (int j = 0; j < 8; j++) acc[i][j] = 0.f;

    const int ar = tid >> 1;
    const int ac4 = (tid & 1) * 4;
    const int br = tid >> 5;
    const int bc = (tid & 31) * 4;

    for (int kt = 0; kt < K_DIM; kt += 8) {
        float4 av = *(const float4*)&g_att[(size_t)(m0 + ar) * K_DIM + kt + ac4];
        float4 bv = *(const float4*)&W[(size_t)(kt + br) * DD + n0 + bc];
        As[ac4 + 0][ar] = av.x;
        As[ac4 + 1][ar] = av.y;
        As[ac4 + 2][ar] = av.z;
        As[ac4 + 3][ar] = av.w;
        *(float4*)&Bs[br][bc] = bv;
        __syncthreads();
#pragma unroll
        for (int kk = 0; kk < 8; kk++) {
            float4 a0 = *(const float4*)&As[kk][ty * 8];
            float4 a1 = *(const float4*)&As[kk][ty * 8 + 4];
            float4 b0 = *(const float4*)&Bs[kk][tx * 8];
            float4 b1 = *(const float4*)&Bs[kk][tx * 8 + 4];
            float af[8] = {a0.x,a0.y,a0.z,a0.w,a1.x,a1.y,a1.z,a1.w};
            float bf[8] = {b0.x,b0.y,b0.z,b0.w,b1.x,b1.y,b1.z,b1.w};
#pragma unroll
            for (int i = 0; i < 8; i++)
#pragma unroll
                for (int j = 0; j < 8; j++)
                    acc[i][j] = fmaf(af[i], bf[j], acc[i][j]);
        }
        __syncthreads();
    }

#pragma unroll
    for (int i = 0; i < 8; i++) {
        int m = m0 + ty * 8 + i;
#pragma unroll
        for (int j = 0; j < 8; j++) {
            int n = n0 + tx * 8 + j;
            out[(size_t)m * DD + n] = acc[i][j] + bias[n];
        }
    }
}

// ============================================================
// Flash attention, fp32, causal. BQ=BK=64, dh=64.
// 256 threads: (tx 0..15, ty 0..15), 4x4 micro-tile.
// smem (dynamic 52224B): Qt[64][68] d-major, KtP[64][68] (K d-major,
// reused as P k-major transposed), Vs[64][68] k-major.
// ============================================================
#define SPAD 68
__global__ __launch_bounds__(256, 2)
void flash_attn_kernel()
{
    extern __shared__ float sm[];
    float* Qt  = sm;                 // Qt[d*SPAD + q]
    float* KtP = sm + 64 * SPAD;     // Kt[d*SPAD + k]  /  Pt[k*SPAD + q]
    float* Vs  = sm + 2 * 64 * SPAD; // Vs[k*SPAD + d]

    const int tid = threadIdx.x;
    const int tx = tid & 15;
    const int ty = tid >> 4;
    const int q0 = blockIdx.x * 64;
    const int bh = blockIdx.y;

    const float* qb = g_q + (size_t)bh * TT * DH;
    const float* kb = g_k + (size_t)bh * TT * DH;
    const float* vb = g_v + (size_t)bh * TT * DH;

    // load Q tile transposed: 1024 float4s, 4 per thread
#pragma unroll
    for (int it = 0; it < 4; it++) {
        int f4 = tid + it * 256;
        int r = f4 >> 4;            // row 0..63
        int c = (f4 & 15) * 4;      // col 0..60
        float4 a = *(const float4*)&qb[(size_t)(q0 + r) * DH + c];
        Qt[(c + 0) * SPAD + r] = a.x;
        Qt[(c + 1) * SPAD + r] = a.y;
        Qt[(c + 2) * SPAD + r] = a.z;
        Qt[(c + 3) * SPAD + r] = a.w;
    }

    float o[4][4];
    float mrow[4], lrow[4];
#pragma unroll
    for (int i = 0; i < 4; i++) {
        mrow[i] = -1e30f; lrow[i] = 0.f;
#pragma unroll
        for (int j = 0; j < 4; j++) o[i][j] = 0.f;
    }

    const int ktmax = q0 / 64;        // diagonal tile index
    for (int kt = 0; kt <= ktmax; kt++) {
        const int k0 = kt * 64;
        __syncthreads();   // previous iter done reading KtP/Vs
        // load K transposed + V direct
#pragma unroll
        for (int it = 0; it < 4; it++) {
            int f4 = tid + it * 256;
            int r = f4 >> 4;
            int c = (f4 & 15) * 4;
            float4 a = *(const float4*)&kb[(size_t)(k0 + r) * DH + c];
            KtP[(c + 0) * SPAD + r] = a.x;
            KtP[(c + 1) * SPAD + r] = a.y;
            KtP[(c + 2) * SPAD + r] = a.z;
            KtP[(c + 3) * SPAD + r] = a.w;
            float4 vv = *(const float4*)&vb[(size_t)(k0 + r) * DH + c];
            *(float4*)&Vs[r * SPAD + c] = vv;
        }
        __syncthreads();

        // S = Q K^T  (4x4 per thread)
        float s[4][4];
#pragma unroll
        for (int i = 0; i < 4; i++)
#pragma unroll
            for (int j = 0; j < 4; j++) s[i][j] = 0.f;
#pragma unroll 8
        for (int d = 0; d < 64; d++) {
            float4 qa = *(const float4*)&Qt[d * SPAD + ty * 4];
            float4 ka = *(const float4*)&KtP[d * SPAD + tx * 4];
            float qf[4] = {qa.x, qa.y, qa.z, qa.w};
            float kf[4] = {ka.x, ka.y, ka.z, ka.w};
#pragma unroll
            for (int i = 0; i < 4; i++)
#pragma unroll
                for (int j = 0; j < 4; j++)
                    s[i][j] = fmaf(qf[i], kf[j], s[i][j]);
        }
        const float sc = 0.125f;   // 1/sqrt(64)
        if (kt == ktmax) {         // diagonal: causal mask
#pragma unroll
            for (int i = 0; i < 4; i++) {
                int qi = q0 + ty * 4 + i;
#pragma unroll
                for (int j = 0; j < 4; j++) {
                    int kj = k0 + tx * 4 + j;
                    s[i][j] = (kj <= qi) ? s[i][j] * sc : -1e30f;
                }
            }
        } else {
#pragma unroll
            for (int i = 0; i < 4; i++)
#pragma unroll
                for (int j = 0; j < 4; j++) s[i][j] *= sc;
        }

        // online softmax update
        float p[4][4];
#pragma unroll
        for (int i = 0; i < 4; i++) {
            float rm = s[i][0];
#pragma unroll
            for (int j = 1; j < 4; j++) rm = fmaxf(rm, s[i][j]);
#pragma unroll
            for (int off = 8; off; off >>= 1)
                rm = fmaxf(rm, __shfl_xor_sync(0xffffffffu, rm, off));
            float mn = fmaxf(mrow[i], rm);
            float corr = __expf(mrow[i] - mn);
            mrow[i] = mn;
            lrow[i] *= corr;
#pragma unroll
            for (int j = 0; j < 4; j++) o[i][j] *= corr;
            float rs = 0.f;
#pragma unroll
            for (int j = 0; j < 4; j++) {
                p[i][j] = __expf(s[i][j] - mn);
                rs += p[i][j];
            }
#pragma unroll
            for (int off = 8; off; off >>= 1)
                rs += __shfl_xor_sync(0xffffffffu, rs, off);
            lrow[i] += rs;
        }

        __syncthreads();   // all threads done reading KtP as K
        // write P transposed: Pt[k][q]
#pragma unroll
        for (int i = 0; i < 4; i++)
#pragma unroll
            for (int j = 0; j < 4; j++)
                KtP[(tx * 4 + j) * SPAD + ty * 4 + i] = p[i][j];
        __syncthreads();

        // O += P @ V
#pragma unroll 8
        for (int kk = 0; kk < 64; kk++) {
            float4 pa = *(const float4*)&KtP[kk * SPAD + ty * 4];
            float4 va = *(const float4*)&Vs[kk * SPAD + tx * 4];
            float pf[4] = {pa.x, pa.y, pa.z, pa.w};
            float vf[4] = {va.x, va.y, va.z, va.w};
#pragma unroll
            for (int i = 0; i < 4; i++)
#pragma unroll
                for (int j = 0; j < 4; j++)
                    o[i][j] = fmaf(pf[i], vf[j], o[i][j]);
        }
    }

    // epilogue: normalize + store to g_att[b][t][h*DH+d]
    const int b = bh / HH;
    const int h = bh % HH;
#pragma unroll
    for (int i = 0; i < 4; i++) {
        int t = q0 + ty * 4 + i;
        float inv = 1.f / lrow[i];
        float* dst = &g_att[((size_t)b * TT + t) * DD + h * DH + tx * 4];
#pragma unroll
        for (int j = 0; j < 4; j++) dst[j] = o[i][j] * inv;
    }
}

// ============================================================
extern "C" void kernel_launch(void* const* d_in, const int* in_sizes, int n_in,
                              void* d_out, int out_size)
{
    const float* x     = (const float*)d_in[0];
    const float* W_qkv = (const float*)d_in[1];
    const float* b_qkv = (const float*)d_in[2];
    const float* W_out = (const float*)d_in[3];
    const float* b_out = (const float*)d_in[4];
    float* out = (float*)d_out;

    // 1) QKV projection + head-split scatter
    dim3 g1(N_QKV / 128, M_ROWS / 128);
    qkv_gemm_kernel<<<g1, 256>>>(x, W_qkv, b_qkv);

    // 2) causal flash attention
    static int smem_set = 0;
    const int smem_bytes = 3 * 64 * SPAD * sizeof(float);  // 52224
    if (!smem_set) {
        cudaFuncSetAttribute(flash_attn_kernel,
                             cudaFuncAttributeMaxDynamicSharedMemorySize,
                             smem_bytes);
        smem_set = 1;
    }
    dim3 g2(TT / 64, BB * HH);
    flash_attn_kernel<<<g2, 256, smem_bytes>>>();

    // 3) output projection
    dim3 g3(DD / 128, M_ROWS / 128);
    out_gemm_kernel<<<g3, 256>>>(W_out, b_out, out);
}

// round 4
// speedup vs baseline: 2.8046x; 2.8046x over previous
#include <cuda_runtime.h>

#define BB 4
#define TT 2048
#define DD 1024
#define HH 16
#define DH 64
#define MROWS (BB*TT)

// -------- scratch (no allocations allowed) --------
__device__ float g_q[BB*HH*TT*DH];    // [b][h][t][d]
__device__ float g_k[BB*HH*TT*DH];
__device__ float g_v[BB*HH*TT*DH];
__device__ float g_att[MROWS*DD];     // [b][t][h*DH+d]

// ---- helpers ----
__device__ __forceinline__ unsigned f2tf(float x) {
    unsigned u;
    asm("cvt.rna.tf32.f32 %0, %1;" : "=r"(u) : "f"(x));
    return u;
}
__device__ __forceinline__ float f2tff(float x) { return __uint_as_float(f2tf(x)); }

__device__ __forceinline__ void mma_tf32(float* d,
                                         unsigned a0, unsigned a1, unsigned a2, unsigned a3,
                                         unsigned b0, unsigned b1)
{
    asm volatile(
        "mma.sync.aligned.m16n8k8.row.col.f32.tf32.tf32.f32 "
        "{%0,%1,%2,%3},{%4,%5,%6,%7},{%8,%9},{%0,%1,%2,%3};\n"
        : "+f"(d[0]), "+f"(d[1]), "+f"(d[2]), "+f"(d[3])
        : "r"(a0), "r"(a1), "r"(a2), "r"(a3), "r"(b0), "r"(b1));
}

// ============================================================
// tf32 MMA GEMM: C[M,N] = A[M,1024] @ W[1024,N] + bias
// block 128x128, kTile 16, 256 thr (8 warps, 2x4), warp 64x32.
// MODE 0: A=x, scatter epilogue to g_q/g_k/g_v (NDIM=3072)
// MODE 1: A=g_att, plain epilogue to out (NDIM=1024)
// smem: As row-major [128][20] (conflict-free A-frag LDS),
//       Bs row-major [16][136] (conflict-free B-frag LDS); double-buffered.
// ============================================================
#define ASTR 20
#define BSTR 136

template<int MODE, int NDIM>
__global__ __launch_bounds__(256)
void mma_gemm(const float* __restrict__ Ain, const float* __restrict__ W,
              const float* __restrict__ bias, float* __restrict__ out)
{
    __shared__ float As[2][128 * ASTR];
    __shared__ float Bs[2][16 * BSTR];

    const float* A = (MODE == 1) ? g_att : Ain;

    const int tid  = threadIdx.x;
    const int lane = tid & 31, warp = tid >> 5;
    const int g = lane >> 2, tig = lane & 3;
    const int wm = warp >> 2, wn = warp & 3;
    const int m0 = blockIdx.y * 128, n0 = blockIdx.x * 128;

    // global->reg load mapping (2 float4 per tensor per thread)
    const int ar = tid >> 2;           // 0..63 (+64 second)
    const int ac = (tid & 3) * 4;
    const int br = tid >> 5;           // 0..7 (+8 second)
    const int bc = (tid & 31) * 4;

    float4 ra0, ra1, rb0, rb1;

#define LDTILE(kt) do {                                                          \
    ra0 = *(const float4*)&A[(size_t)(m0 + ar) * DD + (kt) * 16 + ac];           \
    ra1 = *(const float4*)&A[(size_t)(m0 + ar + 64) * DD + (kt) * 16 + ac];      \
    rb0 = *(const float4*)&W[(size_t)((kt) * 16 + br) * NDIM + n0 + bc];         \
    rb1 = *(const float4*)&W[(size_t)((kt) * 16 + br + 8) * NDIM + n0 + bc];     \
} while (0)

#define STTILE(bf) do {                                                          \
    float4 t;                                                                    \
    t.x = f2tff(ra0.x); t.y = f2tff(ra0.y); t.z = f2tff(ra0.z); t.w = f2tff(ra0.w); \
    *(float4*)&As[bf][ar * ASTR + ac] = t;                                       \
    t.x = f2tff(ra1.x); t.y = f2tff(ra1.y); t.z = f2tff(ra1.z); t.w = f2tff(ra1.w); \
    *(float4*)&As[bf][(ar + 64) * ASTR + ac] = t;                                \
    t.x = f2tff(rb0.x); t.y = f2tff(rb0.y); t.z = f2tff(rb0.z); t.w = f2tff(rb0.w); \
    *(float4*)&Bs[bf][br * BSTR + bc] = t;                                       \
    t.x = f2tff(rb1.x); t.y = f2tff(rb1.y); t.z = f2tff(rb1.z); t.w = f2tff(rb1.w); \
    *(float4*)&Bs[bf][(br + 8) * BSTR + bc] = t;                                 \
} while (0)

    float acc[4][4][4];
#pragma unroll
    for (int i = 0; i < 4; i++)
#pragma unroll
        for (int j = 0; j < 4; j++)
#pragma unroll
            for (int k = 0; k < 4; k++) acc[i][j][k] = 0.f;

    LDTILE(0);
    STTILE(0);
    __syncthreads();

    for (int kt = 0; kt < 64; kt++) {
        const int cur = kt & 1;
        if (kt < 63) LDTILE(kt + 1);

        const float* as = As[cur];
        const float* bs = Bs[cur];
#pragma unroll
        for (int kk = 0; kk < 2; kk++) {
            unsigned bfr[4][2];
#pragma unroll
            for (int ni = 0; ni < 4; ni++) {
                const int nn = wn * 32 + ni * 8 + g;
                bfr[ni][0] = __float_as_uint(bs[(kk * 8 + tig) * BSTR + nn]);
                bfr[ni][1] = __float_as_uint(bs[(kk * 8 + tig + 4) * BSTR + nn]);
            }
#pragma unroll
            for (int mi = 0; mi < 4; mi++) {
                const int mrow = wm * 64 + mi * 16;
                unsigned a0 = __float_as_uint(as[(mrow + g) * ASTR + kk * 8 + tig]);
                unsigned a1 = __float_as_uint(as[(mrow + g + 8) * ASTR + kk * 8 + tig]);
                unsigned a2 = __float_as_uint(as[(mrow + g) * ASTR + kk * 8 + tig + 4]);
                unsigned a3 = __float_as_uint(as[(mrow + g + 8) * ASTR + kk * 8 + tig + 4]);
#pragma unroll
                for (int ni = 0; ni < 4; ni++)
                    mma_tf32(acc[mi][ni], a0, a1, a2, a3, bfr[ni][0], bfr[ni][1]);
            }
        }
        if (kt < 63) STTILE(cur ^ 1);
        __syncthreads();
    }

    // epilogue
#pragma unroll
    for (int mi = 0; mi < 4; mi++) {
        const int m = m0 + wm * 64 + mi * 16 + g;     // rows m and m+8
#pragma unroll
        for (int ni = 0; ni < 4; ni++) {
            const int n = n0 + wn * 32 + ni * 8 + 2 * tig;  // cols n and n+1
            const float bz0 = bias[n], bz1 = bias[n + 1];
            if (MODE == 0) {
                const int sec = n >> 10, nn = n & 1023;
                const int h = nn >> 6, d = nn & 63;
                float* dst = (sec == 0) ? g_q : (sec == 1) ? g_k : g_v;
                const int b = m >> 11, t = m & 2047;
                const size_t base = ((size_t)(b * HH + h) * TT + t) * DH + d;
                dst[base]              = acc[mi][ni][0] + bz0;
                dst[base + 1]          = acc[mi][ni][1] + bz1;
                dst[base + 8 * DH]     = acc[mi][ni][2] + bz0;  // row t+8
                dst[base + 8 * DH + 1] = acc[mi][ni][3] + bz1;
            } else {
                const size_t base = (size_t)m * DD + n;
                out[base]              = acc[mi][ni][0] + bz0;
                out[base + 1]          = acc[mi][ni][1] + bz1;
                out[base + 8 * DD]     = acc[mi][ni][2] + bz0;
                out[base + 8 * DD + 1] = acc[mi][ni][3] + bz1;
            }
        }
    }
#undef LDTILE
#undef STTILE
}

// ============================================================
// Flash attention, tf32 MMA. BQ=128, BK=64, dh=64.
// 256 thr = 8 warps; warp w owns q rows [w*16, w*16+16).
// smem stride 72 floats => all fragment LDS conflict-free.
// P round-trips through per-warp-private smem rows (syncwarp only).
// ============================================================
#define FSTR 72
__global__ __launch_bounds__(256)
void flash_mma()
{
    extern __shared__ float sm[];
    float* Qs = sm;                    // [128][72] (scaled, tf32)
    float* Ks = Qs + 128 * FSTR;       // [64][72]
    float* Vs = Ks + 64 * FSTR;        // [64][72]
    float* Ps = Vs + 64 * FSTR;        // [128][72]

    const int tid  = threadIdx.x;
    const int lane = tid & 31, warp = tid >> 5;
    const int g = lane >> 2, tig = lane & 3;
    const int q0 = blockIdx.x * 128;
    const int bh = blockIdx.y;
    const int qbase = warp * 16;

    const float* qb = g_q + (size_t)bh * TT * DH;
    const float* kb = g_k + (size_t)bh * TT * DH;
    const float* vb = g_v + (size_t)bh * TT * DH;

    // load Q (fold 1/sqrt(64) scale), cvt to tf32
#pragma unroll
    for (int it = 0; it < 8; it++) {
        const int f4 = tid + it * 256;
        const int r = f4 >> 4, c = (f4 & 15) * 4;
        float4 v = *(const float4*)&qb[(size_t)(q0 + r) * DH + c];
        float4 t;
        t.x = f2tff(v.x * 0.125f); t.y = f2tff(v.y * 0.125f);
        t.z = f2tff(v.z * 0.125f); t.w = f2tff(v.w * 0.125f);
        *(float4*)&Qs[r * FSTR + c] = t;
    }

    float o[8][4];
    float mr[2] = {-1e30f, -1e30f}, lr[2] = {0.f, 0.f};
#pragma unroll
    for (int i = 0; i < 8; i++)
#pragma unroll
        for (int j = 0; j < 4; j++) o[i][j] = 0.f;

    const int nkt = (q0 >> 6) + 2;
    for (int kt = 0; kt < nkt; kt++) {
        const int k0 = kt * 64;
        __syncthreads();          // prior iter done with Ks/Vs (and P reads)
#pragma unroll
        for (int it = 0; it < 4; it++) {
            const int f4 = tid + it * 256;
            const int r = f4 >> 4, c = (f4 & 15) * 4;
            float4 kv = *(const float4*)&kb[(size_t)(k0 + r) * DH + c];
            float4 t;
            t.x = f2tff(kv.x); t.y = f2tff(kv.y); t.z = f2tff(kv.z); t.w = f2tff(kv.w);
            *(float4*)&Ks[r * FSTR + c] = t;
            float4 vv = *(const float4*)&vb[(size_t)(k0 + r) * DH + c];
            t.x = f2tff(vv.x); t.y = f2tff(vv.y); t.z = f2tff(vv.z); t.w = f2tff(vv.w);
            *(float4*)&Vs[r * FSTR + c] = t;
        }
        __syncthreads();

        // ---- S = Q K^T (per-warp 16x64) ----
        float s[8][4];
#pragma unroll
        for (int i = 0; i < 8; i++)
#pragma unroll
            for (int j = 0; j < 4; j++) s[i][j] = 0.f;

#pragma unroll
        for (int kk = 0; kk < 8; kk++) {
            unsigned a0 = __float_as_uint(Qs[(qbase + g) * FSTR + kk * 8 + tig]);
            unsigned a1 = __float_as_uint(Qs[(qbase + g + 8) * FSTR + kk * 8 + tig]);
            unsigned a2 = __float_as_uint(Qs[(qbase + g) * FSTR + kk * 8 + tig + 4]);
            unsigned a3 = __float_as_uint(Qs[(qbase + g + 8) * FSTR + kk * 8 + tig + 4]);
#pragma unroll
            for (int ni = 0; ni < 8; ni++) {
                unsigned b0 = __float_as_uint(Ks[(ni * 8 + g) * FSTR + kk * 8 + tig]);
                unsigned b1 = __float_as_uint(Ks[(ni * 8 + g) * FSTR + kk * 8 + tig + 4]);
                mma_tf32(s[ni], a0, a1, a2, a3, b0, b1);
            }
        }

        // ---- causal mask ----
        if (k0 + 63 > q0 + qbase) {
            const int qr0 = q0 + qbase + g, qr1 = qr0 + 8;
#pragma unroll
            for (int ni = 0; ni < 8; ni++) {
                const int key0 = k0 + ni * 8 + 2 * tig;
                if (key0 > qr0)     s[ni][0] = -1e30f;
                if (key0 + 1 > qr0) s[ni][1] = -1e30f;
                if (key0 > qr1)     s[ni][2] = -1e30f;
                if (key0 + 1 > qr1) s[ni][3] = -1e30f;
            }
        }

        // ---- online softmax (rows live inside a quad) ----
        float rm0 = -1e30f, rm1 = -1e30f;
#pragma unroll
        for (int ni = 0; ni < 8; ni++) {
            rm0 = fmaxf(rm0, fmaxf(s[ni][0], s[ni][1]));
            rm1 = fmaxf(rm1, fmaxf(s[ni][2], s[ni][3]));
        }
        rm0 = fmaxf(rm0, __shfl_xor_sync(0xffffffffu, rm0, 1));
        rm0 = fmaxf(rm0, __shfl_xor_sync(0xffffffffu, rm0, 2));
        rm1 = fmaxf(rm1, __shfl_xor_sync(0xffffffffu, rm1, 1));
        rm1 = fmaxf(rm1, __shfl_xor_sync(0xffffffffu, rm1, 2));

        const float mn0 = fmaxf(mr[0], rm0), mn1 = fmaxf(mr[1], rm1);
        const float c0 = __expf(mr[0] - mn0), c1 = __expf(mr[1] - mn1);
        mr[0] = mn0; mr[1] = mn1;
        lr[0] *= c0; lr[1] *= c1;
#pragma unroll
        for (int nj = 0; nj < 8; nj++) {
            o[nj][0] *= c0; o[nj][1] *= c0;
            o[nj][2] *= c1; o[nj][3] *= c1;
        }

        float rs0 = 0.f, rs1 = 0.f;
#pragma unroll
        for (int ni = 0; ni < 8; ni++) {
            const float p0 = __expf(s[ni][0] - mn0);
            const float p1 = __expf(s[ni][1] - mn0);
            const float p2 = __expf(s[ni][2] - mn1);
            const float p3 = __expf(s[ni][3] - mn1);
            rs0 += p0 + p1; rs1 += p2 + p3;
            float2 w0; w0.x = f2tff(p0); w0.y = f2tff(p1);
            float2 w1; w1.x = f2tff(p2); w1.y = f2tff(p3);
            *(float2*)&Ps[(qbase + g) * FSTR + ni * 8 + 2 * tig] = w0;
            *(float2*)&Ps[(qbase + g + 8) * FSTR + ni * 8 + 2 * tig] = w1;
        }
        rs0 += __shfl_xor_sync(0xffffffffu, rs0, 1);
        rs0 += __shfl_xor_sync(0xffffffffu, rs0, 2);
        rs1 += __shfl_xor_sync(0xffffffffu, rs1, 1);
        rs1 += __shfl_xor_sync(0xffffffffu, rs1, 2);
        lr[0] += rs0; lr[1] += rs1;

        __syncwarp();   // P rows are warp-private: warp-level sync suffices

        // ---- O += P V (per-warp 16x64) ----
#pragma unroll
        for (int kk = 0; kk < 8; kk++) {
            unsigned a0 = __float_as_uint(Ps[(qbase + g) * FSTR + kk * 8 + tig]);
            unsigned a1 = __float_as_uint(Ps[(qbase + g + 8) * FSTR + kk * 8 + tig]);
            unsigned a2 = __float_as_uint(Ps[(qbase + g) * FSTR + kk * 8 + tig + 4]);
            unsigned a3 = __float_as_uint(Ps[(qbase + g + 8) * FSTR + kk * 8 + tig + 4]);
#pragma unroll
            for (int nj = 0; nj < 8; nj++) {
                unsigned b0 = __float_as_uint(Vs[(kk * 8 + tig) * FSTR + nj * 8 + g]);
                unsigned b1 = __float_as_uint(Vs[(kk * 8 + tig + 4) * FSTR + nj * 8 + g]);
                mma_tf32(o[nj], a0, a1, a2, a3, b0, b1);
            }
        }
    }

    // epilogue: normalize, store to g_att[b][t][h*64+d]
    const float inv0 = 1.f / lr[0], inv1 = 1.f / lr[1];
    const int b = bh >> 4, h = bh & 15;
    const int t0 = q0 + qbase + g;
#pragma unroll
    for (int nj = 0; nj < 8; nj++) {
        const size_t base = ((size_t)b * TT + t0) * DD + h * DH + nj * 8 + 2 * tig;
        float2 w0; w0.x = o[nj][0] * inv0; w0.y = o[nj][1] * inv0;
        float2 w1; w1.x = o[nj][2] * inv1; w1.y = o[nj][3] * inv1;
        *(float2*)&g_att[base] = w0;
        *(float2*)&g_att[base + (size_t)8 * DD] = w1;   // row t0+8
    }
}

// ============================================================
extern "C" void kernel_launch(void* const* d_in, const int* in_sizes, int n_in,
                              void* d_out, int out_size)
{
    const float* x     = (const float*)d_in[0];
    const float* W_qkv = (const float*)d_in[1];
    const float* b_qkv = (const float*)d_in[2];
    const float* W_out = (const float*)d_in[3];
    const float* b_out = (const float*)d_in[4];
    float* out = (float*)d_out;

    // 1) QKV projection (tf32 MMA) + head-split scatter
    dim3 g1(3 * DD / 128, MROWS / 128);   // 24 x 64
    mma_gemm<0, 3 * DD><<<g1, 256>>>(x, W_qkv, b_qkv, nullptr);

    // 2) causal flash attention (tf32 MMA)
    static int smem_set = 0;
    const int smem_bytes = (128 * FSTR + 64 * FSTR + 64 * FSTR + 128 * FSTR) * 4; // 110592
    if (!smem_set) {
        cudaFuncSetAttribute(flash_mma,
                             cudaFuncAttributeMaxDynamicSharedMemorySize, smem_bytes);
        smem_set = 1;
    }
    dim3 g2(TT / 128, BB * HH);           // 16 x 64
    flash_mma<<<g2, 256, smem_bytes>>>();

    // 3) output projection (tf32 MMA)
    dim3 g3(DD / 128, MROWS / 128);       // 8 x 64
    mma_gemm<1, DD><<<g3, 256>>>(nullptr, W_out, b_out, out);
}

// round 5
// speedup vs baseline: 3.2230x; 1.1492x over previous
#include <cuda_runtime.h>

#define BB 4
#define TT 2048
#define DD 1024
#define HH 16
#define DH 64
#define MROWS (BB*TT)

// -------- scratch (no allocations allowed) --------
__device__ float g_q[BB*HH*TT*DH];    // [b][h][t][d]
__device__ float g_k[BB*HH*TT*DH];
__device__ float g_v[BB*HH*TT*DH];
__device__ float g_att[MROWS*DD];     // [b][t][h*DH+d]

// ---- helpers ----
__device__ __forceinline__ unsigned f2tf(float x) {
    unsigned u;
    asm("cvt.rna.tf32.f32 %0, %1;" : "=r"(u) : "f"(x));
    return u;
}
__device__ __forceinline__ float f2tff(float x) { return __uint_as_float(f2tf(x)); }
__device__ __forceinline__ float4 cvt4(float4 v) {
    float4 t;
    t.x = f2tff(v.x); t.y = f2tff(v.y); t.z = f2tff(v.z); t.w = f2tff(v.w);
    return t;
}

__device__ __forceinline__ void mma_tf32(float* d,
                                         unsigned a0, unsigned a1, unsigned a2, unsigned a3,
                                         unsigned b0, unsigned b1)
{
    asm volatile(
        "mma.sync.aligned.m16n8k8.row.col.f32.tf32.tf32.f32 "
        "{%0,%1,%2,%3},{%4,%5,%6,%7},{%8,%9},{%0,%1,%2,%3};\n"
        : "+f"(d[0]), "+f"(d[1]), "+f"(d[2]), "+f"(d[3])
        : "r"(a0), "r"(a1), "r"(a2), "r"(a3), "r"(b0), "r"(b1));
}

// ============================================================
// tf32 MMA GEMM: C[M,N] = A[M,1024] @ W[1024,N] + bias
// block 128(M) x 256(N), kTile 16, 256 thr = 8 warps (2x4),
// warp tile 64x64 (mi=4 x ni=8 MMAs of m16n8k8).
// MODE 0: A=x, scatter epilogue to g_q/g_k/g_v (NDIM=3072)
// MODE 1: A=g_att, plain epilogue to out (NDIM=1024)
// smem dynamic: As[2][128*20], Bs[2][16*264]; both frag-LDS conflict-free.
// ============================================================
#define ASTR 20
#define BSTR 264

template<int MODE, int NDIM>
__global__ __launch_bounds__(256)
void mma_gemm(const float* __restrict__ Ain, const float* __restrict__ W,
              const float* __restrict__ bias, float* __restrict__ out)
{
    extern __shared__ float smg[];
    float* As = smg;                       // [2][128*ASTR]
    float* Bs = smg + 2 * 128 * ASTR;      // [2][16*BSTR]

    const float* A = (MODE == 1) ? g_att : Ain;

    const int tid  = threadIdx.x;
    const int lane = tid & 31, warp = tid >> 5;
    const int g = lane >> 2, tig = lane & 3;
    const int wm = warp >> 2, wn = warp & 3;
    const int m0 = blockIdx.y * 128, n0 = blockIdx.x * 256;

    // global->reg load mappings
    const int arow = tid >> 2;            // rows arow, arow+64
    const int acol = (tid & 3) * 4;
    const int brow = tid >> 6;            // rows brow+4j, j=0..3
    const int bcol = (tid & 63) * 4;

    float4 ra[2], rb[4];

#define LDTILE(kt) do {                                                           \
    ra[0] = *(const float4*)&A[(size_t)(m0 + arow) * DD + (kt) * 16 + acol];      \
    ra[1] = *(const float4*)&A[(size_t)(m0 + arow + 64) * DD + (kt) * 16 + acol]; \
    rb[0] = *(const float4*)&W[(size_t)((kt) * 16 + brow +  0) * NDIM + n0 + bcol]; \
    rb[1] = *(const float4*)&W[(size_t)((kt) * 16 + brow +  4) * NDIM + n0 + bcol]; \
    rb[2] = *(const float4*)&W[(size_t)((kt) * 16 + brow +  8) * NDIM + n0 + bcol]; \
    rb[3] = *(const float4*)&W[(size_t)((kt) * 16 + brow + 12) * NDIM + n0 + bcol]; \
} while (0)

#define STTILE(bf) do {                                                           \
    float* as = As + (bf) * 128 * ASTR;                                           \
    float* bs = Bs + (bf) * 16 * BSTR;                                            \
    *(float4*)&as[arow * ASTR + acol]        = cvt4(ra[0]);                       \
    *(float4*)&as[(arow + 64) * ASTR + acol] = cvt4(ra[1]);                       \
    *(float4*)&bs[(brow +  0) * BSTR + bcol] = cvt4(rb[0]);                       \
    *(float4*)&bs[(brow +  4) * BSTR + bcol] = cvt4(rb[1]);                       \
    *(float4*)&bs[(brow +  8) * BSTR + bcol] = cvt4(rb[2]);                       \
    *(float4*)&bs[(brow + 12) * BSTR + bcol] = cvt4(rb[3]);                       \
} while (0)

    float acc[4][8][4];
#pragma unroll
    for (int i = 0; i < 4; i++)
#pragma unroll
        for (int j = 0; j < 8; j++)
#pragma unroll
            for (int k = 0; k < 4; k++) acc[i][j][k] = 0.f;

    LDTILE(0);
    STTILE(0);
    __syncthreads();

    for (int kt = 0; kt < 64; kt++) {
        const int cur = kt & 1;
        if (kt < 63) LDTILE(kt + 1);

        const float* as = As + cur * 128 * ASTR;
        const float* bs = Bs + cur * 16 * BSTR;
#pragma unroll
        for (int kk = 0; kk < 2; kk++) {
            unsigned bfr[8][2];
#pragma unroll
            for (int ni = 0; ni < 8; ni++) {
                const int nn = wn * 64 + ni * 8 + g;
                bfr[ni][0] = __float_as_uint(bs[(kk * 8 + tig) * BSTR + nn]);
                bfr[ni][1] = __float_as_uint(bs[(kk * 8 + tig + 4) * BSTR + nn]);
            }
#pragma unroll
            for (int mi = 0; mi < 4; mi++) {
                const int mrow = wm * 64 + mi * 16;
                unsigned a0 = __float_as_uint(as[(mrow + g) * ASTR + kk * 8 + tig]);
                unsigned a1 = __float_as_uint(as[(mrow + g + 8) * ASTR + kk * 8 + tig]);
                unsigned a2 = __float_as_uint(as[(mrow + g) * ASTR + kk * 8 + tig + 4]);
                unsigned a3 = __float_as_uint(as[(mrow + g + 8) * ASTR + kk * 8 + tig + 4]);
#pragma unroll
                for (int ni = 0; ni < 8; ni++)
                    mma_tf32(acc[mi][ni], a0, a1, a2, a3, bfr[ni][0], bfr[ni][1]);
            }
        }
        if (kt < 63) STTILE(cur ^ 1);
        __syncthreads();
    }

    // epilogue
#pragma unroll
    for (int mi = 0; mi < 4; mi++) {
        const int m = m0 + wm * 64 + mi * 16 + g;     // rows m and m+8
#pragma unroll
        for (int ni = 0; ni < 8; ni++) {
            const int n = n0 + wn * 64 + ni * 8 + 2 * tig;  // cols n, n+1
            const float bz0 = bias[n], bz1 = bias[n + 1];
            if (MODE == 0) {
                const int sec = n >> 10, nn = n & 1023;
                const int h = nn >> 6, d = nn & 63;
                float* dst = (sec == 0) ? g_q : (sec == 1) ? g_k : g_v;
                const int b = m >> 11, t = m & 2047;
                const size_t base = ((size_t)(b * HH + h) * TT + t) * DH + d;
                dst[base]              = acc[mi][ni][0] + bz0;
                dst[base + 1]          = acc[mi][ni][1] + bz1;
                dst[base + 8 * DH]     = acc[mi][ni][2] + bz0;  // row t+8
                dst[base + 8 * DH + 1] = acc[mi][ni][3] + bz1;
            } else {
                const size_t base = (size_t)m * DD + n;
                out[base]              = acc[mi][ni][0] + bz0;
                out[base + 1]          = acc[mi][ni][1] + bz1;
                out[base + 8 * DD]     = acc[mi][ni][2] + bz0;
                out[base + 8 * DD + 1] = acc[mi][ni][3] + bz1;
            }
        }
    }
#undef LDTILE
#undef STTILE
}

// ============================================================
// Flash attention, tf32 MMA. BQ=128, BK=64, dh=64.
// 128 thr = 4 warps; warp w owns q rows [w*32, w*32+32).
// Q fragments + O accumulators live in registers for the whole loop.
// smem: QPs[128][72] (Q staging, then P), Ks[64][72], Vs[64][72].
// ============================================================
#define FSTR 72
__global__ __launch_bounds__(128)
void flash_mma()
{
    extern __shared__ float sm[];
    float* QPs = sm;                   // [128][FSTR]: Q staging -> P buffer
    float* Ks  = sm + 128 * FSTR;      // [64][FSTR]
    float* Vs  = Ks + 64 * FSTR;       // [64][FSTR]

    const int tid  = threadIdx.x;
    const int lane = tid & 31, warp = tid >> 5;
    const int g = lane >> 2, tig = lane & 3;
    const int q0 = blockIdx.x * 128;
    const int bh = blockIdx.y;
    const int qbase = warp * 32;

    const float* qb = g_q + (size_t)bh * TT * DH;
    const float* kb = g_k + (size_t)bh * TT * DH;
    const float* vb = g_v + (size_t)bh * TT * DH;

    // stage Q (fold 1/sqrt(64)), cvt tf32
#pragma unroll
    for (int it = 0; it < 16; it++) {
        const int i = tid + it * 128;
        const int r = i >> 4, c = (i & 15) * 4;
        float4 v = *(const float4*)&qb[(size_t)(q0 + r) * DH + c];
        float4 t;
        t.x = f2tff(v.x * 0.125f); t.y = f2tff(v.y * 0.125f);
        t.z = f2tff(v.z * 0.125f); t.w = f2tff(v.w * 0.125f);
        *(float4*)&QPs[r * FSTR + c] = t;
    }
    __syncthreads();

    // hoist Q fragments to registers (warp-own rows only)
    unsigned qf[8][2][4];
#pragma unroll
    for (int kk = 0; kk < 8; kk++)
#pragma unroll
        for (int mi = 0; mi < 2; mi++) {
            const int r = qbase + mi * 16;
            qf[kk][mi][0] = __float_as_uint(QPs[(r + g) * FSTR + kk * 8 + tig]);
            qf[kk][mi][1] = __float_as_uint(QPs[(r + g + 8) * FSTR + kk * 8 + tig]);
            qf[kk][mi][2] = __float_as_uint(QPs[(r + g) * FSTR + kk * 8 + tig + 4]);
            qf[kk][mi][3] = __float_as_uint(QPs[(r + g + 8) * FSTR + kk * 8 + tig + 4]);
        }
    // QPs now reusable as P (warp reads/writes only its own 32 rows)

    float o[2][8][4];
    float mr[2][2], lr[2][2];
#pragma unroll
    for (int mi = 0; mi < 2; mi++) {
        mr[mi][0] = mr[mi][1] = -1e30f;
        lr[mi][0] = lr[mi][1] = 0.f;
#pragma unroll
        for (int j = 0; j < 8; j++)
#pragma unroll
            for (int k = 0; k < 4; k++) o[mi][j][k] = 0.f;
    }

    const int nkt = (q0 >> 6) + 2;
    for (int kt = 0; kt < nkt; kt++) {
        const int k0 = kt * 64;
        __syncthreads();                // prior iter done reading Ks/Vs
#pragma unroll
        for (int it = 0; it < 8; it++) {
            const int i = tid + it * 128;
            const int r = i >> 4, c = (i & 15) * 4;
            *(float4*)&Ks[r * FSTR + c] = cvt4(*(const float4*)&kb[(size_t)(k0 + r) * DH + c]);
            *(float4*)&Vs[r * FSTR + c] = cvt4(*(const float4*)&vb[(size_t)(k0 + r) * DH + c]);
        }
        __syncthreads();

        if (k0 > q0 + qbase + 31) continue;   // warp fully masked (syncs already done)

        // ---- S = Q K^T (warp 32x64) ----
        float s[2][8][4];
#pragma unroll
        for (int mi = 0; mi < 2; mi++)
#pragma unroll
            for (int i = 0; i < 8; i++)
#pragma unroll
                for (int j = 0; j < 4; j++) s[mi][i][j] = 0.f;

#pragma unroll
        for (int kk = 0; kk < 8; kk++) {
            unsigned bfr[8][2];
#pragma unroll
            for (int ni = 0; ni < 8; ni++) {
                bfr[ni][0] = __float_as_uint(Ks[(ni * 8 + g) * FSTR + kk * 8 + tig]);
                bfr[ni][1] = __float_as_uint(Ks[(ni * 8 + g) * FSTR + kk * 8 + tig + 4]);
            }
#pragma unroll
            for (int mi = 0; mi < 2; mi++)
#pragma unroll
                for (int ni = 0; ni < 8; ni++)
                    mma_tf32(s[mi][ni], qf[kk][mi][0], qf[kk][mi][1],
                             qf[kk][mi][2], qf[kk][mi][3], bfr[ni][0], bfr[ni][1]);
        }

        // ---- causal mask (per 16-row sub-tile) ----
#pragma unroll
        for (int mi = 0; mi < 2; mi++) {
            if (k0 + 63 > q0 + qbase + mi * 16) {
                const int qr0 = q0 + qbase + mi * 16 + g, qr1 = qr0 + 8;
#pragma unroll
                for (int ni = 0; ni < 8; ni++) {
                    const int key0 = k0 + ni * 8 + 2 * tig;
                    if (key0 > qr0)     s[mi][ni][0] = -1e30f;
                    if (key0 + 1 > qr0) s[mi][ni][1] = -1e30f;
                    if (key0 > qr1)     s[mi][ni][2] = -1e30f;
                    if (key0 + 1 > qr1) s[mi][ni][3] = -1e30f;
                }
            }
        }

        // ---- online softmax + write P ----
#pragma unroll
        for (int mi = 0; mi < 2; mi++) {
            float rm0 = -1e30f, rm1 = -1e30f;
#pragma unroll
            for (int ni = 0; ni < 8; ni++) {
                rm0 = fmaxf(rm0, fmaxf(s[mi][ni][0], s[mi][ni][1]));
                rm1 = fmaxf(rm1, fmaxf(s[mi][ni][2], s[mi][ni][3]));
            }
            rm0 = fmaxf(rm0, __shfl_xor_sync(0xffffffffu, rm0, 1));
            rm0 = fmaxf(rm0, __shfl_xor_sync(0xffffffffu, rm0, 2));
            rm1 = fmaxf(rm1, __shfl_xor_sync(0xffffffffu, rm1, 1));
            rm1 = fmaxf(rm1, __shfl_xor_sync(0xffffffffu, rm1, 2));

            const float mn0 = fmaxf(mr[mi][0], rm0), mn1 = fmaxf(mr[mi][1], rm1);
            const float c0 = __expf(mr[mi][0] - mn0), c1 = __expf(mr[mi][1] - mn1);
            mr[mi][0] = mn0; mr[mi][1] = mn1;
            lr[mi][0] *= c0; lr[mi][1] *= c1;
#pragma unroll
            for (int nj = 0; nj < 8; nj++) {
                o[mi][nj][0] *= c0; o[mi][nj][1] *= c0;
                o[mi][nj][2] *= c1; o[mi][nj][3] *= c1;
            }

            float rs0 = 0.f, rs1 = 0.f;
            const int pr = qbase + mi * 16;
#pragma unroll
            for (int ni = 0; ni < 8; ni++) {
                const float p0 = __expf(s[mi][ni][0] - mn0);
                const float p1 = __expf(s[mi][ni][1] - mn0);
                const float p2 = __expf(s[mi][ni][2] - mn1);
                const float p3 = __expf(s[mi][ni][3] - mn1);
                rs0 += p0 + p1; rs1 += p2 + p3;
                float2 w0; w0.x = f2tff(p0); w0.y = f2tff(p1);
                float2 w1; w1.x = f2tff(p2); w1.y = f2tff(p3);
                *(float2*)&QPs[(pr + g) * FSTR + ni * 8 + 2 * tig] = w0;
                *(float2*)&QPs[(pr + g + 8) * FSTR + ni * 8 + 2 * tig] = w1;
            }
            rs0 += __shfl_xor_sync(0xffffffffu, rs0, 1);
            rs0 += __shfl_xor_sync(0xffffffffu, rs0, 2);
            rs1 += __shfl_xor_sync(0xffffffffu, rs1, 1);
            rs1 += __shfl_xor_sync(0xffffffffu, rs1, 2);
            lr[mi][0] += rs0; lr[mi][1] += rs1;
        }

        __syncwarp();   // P rows are warp-private

        // ---- O += P V (warp 32x64) ----
#pragma unroll
        for (int kk = 0; kk < 8; kk++) {
            unsigned vfr[8][2];
#pragma unroll
            for (int nj = 0; nj < 8; nj++) {
                vfr[nj][0] = __float_as_uint(Vs[(kk * 8 + tig) * FSTR + nj * 8 + g]);
                vfr[nj][1] = __float_as_uint(Vs[(kk * 8 + tig + 4) * FSTR + nj * 8 + g]);
            }
#pragma unroll
            for (int mi = 0; mi < 2; mi++) {
                const int pr = qbase + mi * 16;
                unsigned a0 = __float_as_uint(QPs[(pr + g) * FSTR + kk * 8 + tig]);
                unsigned a1 = __float_as_uint(QPs[(pr + g + 8) * FSTR + kk * 8 + tig]);
                unsigned a2 = __float_as_uint(QPs[(pr + g) * FSTR + kk * 8 + tig + 4]);
                unsigned a3 = __float_as_uint(QPs[(pr + g + 8) * FSTR + kk * 8 + tig + 4]);
#pragma unroll
                for (int nj = 0; nj < 8; nj++)
                    mma_tf32(o[mi][nj], a0, a1, a2, a3, vfr[nj][0], vfr[nj][1]);
            }
        }
    }

    // epilogue: normalize, store to g_att[b][t][h*64+d]
    const int b = bh >> 4, h = bh & 15;
#pragma unroll
    for (int mi = 0; mi < 2; mi++) {
        const float inv0 = 1.f / lr[mi][0], inv1 = 1.f / lr[mi][1];
        const int t0 = q0 + qbase + mi * 16 + g;
#pragma unroll
        for (int nj = 0; nj < 8; nj++) {
            const size_t base = ((size_t)b * TT + t0) * DD + h * DH + nj * 8 + 2 * tig;
            float2 w0; w0.x = o[mi][nj][0] * inv0; w0.y = o[mi][nj][1] * inv0;
            float2 w1; w1.x = o[mi][nj][2] * inv1; w1.y = o[mi][nj][3] * inv1;
            *(float2*)&g_att[base] = w0;
            *(float2*)&g_att[base + (size_t)8 * DD] = w1;   // row t0+8
        }
    }
}

// ============================================================
extern "C" void kernel_launch(void* const* d_in, const int* in_sizes, int n_in,
                              void* d_out, int out_size)
{
    const float* x     = (const float*)d_in[0];
    const float* W_qkv = (const float*)d_in[1];
    const float* b_qkv = (const float*)d_in[2];
    const float* W_out = (const float*)d_in[3];
    const float* b_out = (const float*)d_in[4];
    float* out = (float*)d_out;

    const int gemm_smem  = (2 * 128 * ASTR + 2 * 16 * BSTR) * 4;   // 54272
    const int flash_smem = (128 * FSTR + 64 * FSTR + 64 * FSTR) * 4; // 73728

    static int attr_set = 0;
    if (!attr_set) {
        cudaFuncSetAttribute(mma_gemm<0, 3 * DD>,
                             cudaFuncAttributeMaxDynamicSharedMemorySize, gemm_smem);
        cudaFuncSetAttribute(mma_gemm<1, DD>,
                             cudaFuncAttributeMaxDynamicSharedMemorySize, gemm_smem);
        cudaFuncSetAttribute(flash_mma,
                             cudaFuncAttributeMaxDynamicSharedMemorySize, flash_smem);
        attr_set = 1;
    }

    // 1) QKV projection (tf32 MMA) + head-split scatter
    dim3 g1(3 * DD / 256, MROWS / 128);   // 12 x 64
    mma_gemm<0, 3 * DD><<<g1, 256, gemm_smem>>>(x, W_qkv, b_qkv, nullptr);

    // 2) causal flash attention (tf32 MMA)
    dim3 g2(TT / 128, BB * HH);           // 16 x 64
    flash_mma<<<g2, 128, flash_smem>>>();

    // 3) output projection (tf32 MMA)
    dim3 g3(DD / 256, MROWS / 128);       // 4 x 64
    mma_gemm<1, DD><<<g3, 256, gemm_smem>>>(nullptr, W_out, b_out, out);
}

// round 7
// speedup vs baseline: 6.8905x; 2.1379x over previous
#include <cuda_runtime.h>
#include <cuda_fp16.h>
#include <cstdint>

#define BB 4
#define TT 2048
#define DD 1024
#define HH 16
#define DH 64
#define MROWS (BB*TT)

// -------- scratch (no allocations allowed) --------
__device__ __half g_q[BB*HH*TT*DH];    // [b][h][t][d]
__device__ __half g_k[BB*HH*TT*DH];
__device__ __half g_v[BB*HH*TT*DH];
__device__ __half g_att[MROWS*DD];     // [b][t][h*DH+d]
__device__ __half g_wqkvT[3*DD*DD];    // W_qkv^T [3072][1024] half
__device__ __half g_woutT[DD*DD];      // W_out^T [1024][1024] half

// ================= helpers =================
__device__ __forceinline__ uint32_t smem_u32(const void* p) {
    uint32_t a;
    asm("{ .reg .u64 t; cvta.to.shared.u64 t, %1; cvt.u32.u64 %0, t; }" : "=r"(a) : "l"(p));
    return a;
}
__device__ __forceinline__ uint32_t f22u(float a, float b) {
    __half2 h = __floats2half2_rn(a, b);
    return *reinterpret_cast<uint32_t*>(&h);
}

__device__ __forceinline__ void mma_f16(float* d,
                                        uint32_t a0, uint32_t a1, uint32_t a2, uint32_t a3,
                                        uint32_t b0, uint32_t b1)
{
    asm volatile(
        "mma.sync.aligned.m16n8k16.row.col.f32.f16.f16.f32 "
        "{%0,%1,%2,%3},{%4,%5,%6,%7},{%8,%9},{%0,%1,%2,%3};\n"
        : "+f"(d[0]), "+f"(d[1]), "+f"(d[2]), "+f"(d[3])
        : "r"(a0), "r"(a1), "r"(a2), "r"(a3), "r"(b0), "r"(b1));
}

#define LDM_X4(r, addr) \
    asm volatile("ldmatrix.sync.aligned.m8n8.x4.shared.b16 {%0,%1,%2,%3}, [%4];" \
                 : "=r"((r)[0]), "=r"((r)[1]), "=r"((r)[2]), "=r"((r)[3]) : "r"(addr))
#define LDM_X4T(r, addr) \
    asm volatile("ldmatrix.sync.aligned.m8n8.x4.trans.shared.b16 {%0,%1,%2,%3}, [%4];" \
                 : "=r"((r)[0]), "=r"((r)[1]), "=r"((r)[2]), "=r"((r)[3]) : "r"(addr))

// ============================================================
// Pre-pass: dst[n][k] = half(src[k][n]).  block (32,8)
// ============================================================
__global__ void transpose_cvt(const float* __restrict__ src, __half* __restrict__ dst,
                              int K, int N)
{
    __shared__ float t[32][33];
    const int bx = blockIdx.x * 32;   // n
    const int by = blockIdx.y * 32;   // k
    const int x = threadIdx.x, y = threadIdx.y;
#pragma unroll
    for (int j = 0; j < 32; j += 8)
        t[y + j][x] = src[(size_t)(by + y + j) * N + bx + x];
    __syncthreads();
#pragma unroll
    for (int j = 0; j < 32; j += 8)
        dst[(size_t)(bx + y + j) * K + by + x] = __float2half_rn(t[x][y + j]);
}

// ============================================================
// fp16 MMA GEMM: C[M,N] = A[M,1024] @ BT^T + bias
// block 128(M) x 256(N), kTile 32, 256 thr = 8 warps (2x4),
// warp 64x64, HMMA m16n8k16, fragments via ldmatrix.x4.
// MODE 0: A = x (fp32, cvt in loader), scatter-to-half g_q/g_k/g_v.
// MODE 1: A = g_att (half), fp32 out.
// smem (dyn, dbl-buf): A[128][40]h, B[256][40]h  (30720 B / buf)
// ============================================================
#define GASTR 40
#define GBUFB 30720

template<int MODE>
__global__ __launch_bounds__(256, 1)
void h_gemm(const float* __restrict__ Af, const __half* __restrict__ Ah,
            const __half* __restrict__ BT, const float* __restrict__ bias,
            float* __restrict__ outf)
{
    extern __shared__ __align__(16) char smc[];
    __half* smh = (__half*)smc;
    const uint32_t sb = smem_u32(smc);

    const int tid = threadIdx.x;
    const int lane = tid & 31, warp = tid >> 5;
    const int g = lane >> 2, tig = lane & 3;
    const int wm = warp >> 2, wn = warp & 3;
    const int m0 = blockIdx.y * 128, n0 = blockIdx.x * 256;

    // lane maps for ldmatrix
    const int l15 = lane & 15, hi8 = (lane >> 4) * 8;
    const int bl = (lane & 7) + (lane >> 4) * 8;         // B/n row
    const int bk = ((lane >> 3) & 1) * 8;                // B k-half

    // loader regs
    float4 raf[4];   // MODE 0
    uint4  rah[2];   // MODE 1
    uint4  rbv[4];

#define LDTILE(kt) do {                                                            \
    const int k0 = (kt) * 32;                                                      \
    if (MODE == 0) {                                                               \
        _Pragma("unroll")                                                          \
        for (int it = 0; it < 4; it++) {                                           \
            const int i = tid + it * 256;                                          \
            const int r = i >> 3, c4 = (i & 7) * 4;                                \
            raf[it] = *(const float4*)&Af[(size_t)(m0 + r) * DD + k0 + c4];        \
        }                                                                          \
    } else {                                                                       \
        _Pragma("unroll")                                                          \
        for (int it = 0; it < 2; it++) {                                           \
            const int i = tid + it * 256;                                          \
            const int r = i >> 2, c8 = (i & 3) * 8;                                \
            rah[it] = *(const uint4*)&Ah[(size_t)(m0 + r) * DD + k0 + c8];         \
        }                                                                          \
    }                                                                              \
    _Pragma("unroll")                                                              \
    for (int it = 0; it < 4; it++) {                                               \
        const int i = tid + it * 256;                                              \
        const int r = i >> 2, c8 = (i & 3) * 8;                                    \
        rbv[it] = *(const uint4*)&BT[(size_t)(n0 + r) * DD + k0 + c8];             \
    }                                                                              \
} while (0)

#define STTILE(bf) do {                                                            \
    __half* sa = smh + (bf) * (GBUFB / 2);                                         \
    __half* sbp = sa + 128 * GASTR;                                                \
    if (MODE == 0) {                                                               \
        _Pragma("unroll")                                                          \
        for (int it = 0; it < 4; it++) {                                           \
            const int i = tid + it * 256;                                          \
            const int r = i >> 3, c4 = (i & 7) * 4;                                \
            uint2 u;                                                               \
            u.x = f22u(raf[it].x, raf[it].y);                                      \
            u.y = f22u(raf[it].z, raf[it].w);                                      \
            *(uint2*)&sa[r * GASTR + c4] = u;                                      \
        }                                                                          \
    } else {                                                                       \
        _Pragma("unroll")                                                          \
        for (int it = 0; it < 2; it++) {                                           \
            const int i = tid + it * 256;                                          \
            const int r = i >> 2, c8 = (i & 3) * 8;                                \
            *(uint4*)&sa[r * GASTR + c8] = rah[it];                                \
        }                                                                          \
    }                                                                              \
    _Pragma("unroll")                                                              \
    for (int it = 0; it < 4; it++) {                                               \
        const int i = tid + it * 256;                                              \
        const int r = i >> 2, c8 = (i & 3) * 8;                                    \
        *(uint4*)&sbp[r * GASTR + c8] = rbv[it];                                   \
    }                                                                              \
} while (0)

    float acc[4][8][4];
#pragma unroll
    for (int i = 0; i < 4; i++)
#pragma unroll
        for (int j = 0; j < 8; j++)
#pragma unroll
            for (int k = 0; k < 4; k++) acc[i][j][k] = 0.f;

    LDTILE(0);
    STTILE(0);
    __syncthreads();

    for (int kt = 0; kt < 32; kt++) {
        const int cur = kt & 1;
        if (kt < 31) LDTILE(kt + 1);

        const uint32_t abase = sb + cur * GBUFB;
        const uint32_t bbase = abase + 128 * GASTR * 2;
#pragma unroll
        for (int kk = 0; kk < 2; kk++) {
            uint32_t af[4][4];
#pragma unroll
            for (int mi = 0; mi < 4; mi++) {
                const int row = wm * 64 + mi * 16 + l15;
                LDM_X4(af[mi], abase + (uint32_t)(row * GASTR + kk * 16 + hi8) * 2);
            }
            uint32_t bf[8][2];
#pragma unroll
            for (int njp = 0; njp < 4; njp++) {
                uint32_t t[4];
                const int row = wn * 64 + njp * 16 + bl;
                LDM_X4(t, bbase + (uint32_t)(row * GASTR + kk * 16 + bk) * 2);
                bf[2 * njp][0] = t[0]; bf[2 * njp][1] = t[1];
                bf[2 * njp + 1][0] = t[2]; bf[2 * njp + 1][1] = t[3];
            }
#pragma unroll
            for (int mi = 0; mi < 4; mi++)
#pragma unroll
                for (int nj = 0; nj < 8; nj++)
                    mma_f16(acc[mi][nj], af[mi][0], af[mi][1], af[mi][2], af[mi][3],
                            bf[nj][0], bf[nj][1]);
        }
        if (kt < 31) STTILE(cur ^ 1);
        __syncthreads();
    }

    // epilogue
#pragma unroll
    for (int mi = 0; mi < 4; mi++) {
        const int m = m0 + wm * 64 + mi * 16 + g;     // rows m, m+8
#pragma unroll
        for (int nj = 0; nj < 8; nj++) {
            const int n = n0 + wn * 64 + nj * 8 + 2 * tig;   // cols n, n+1
            const float bz0 = __ldg(&bias[n]), bz1 = __ldg(&bias[n + 1]);
            const float v0 = acc[mi][nj][0] + bz0, v1 = acc[mi][nj][1] + bz1;
            const float v2 = acc[mi][nj][2] + bz0, v3 = acc[mi][nj][3] + bz1;
            if (MODE == 0) {
                const int sec = n >> 10, nn = n & 1023;
                const int h = nn >> 6, d = nn & 63;
                __half* dst = (sec == 0) ? g_q : (sec == 1) ? g_k : g_v;
                const size_t base = ((size_t)(m >> 11) * HH + h) * ((size_t)TT * DH)
                                  + (size_t)(m & 2047) * DH + d;
                *(__half2*)&dst[base]           = __floats2half2_rn(v0, v1);
                *(__half2*)&dst[base + 8 * DH]  = __floats2half2_rn(v2, v3);
            } else {
                float2 w0; w0.x = v0; w0.y = v1;
                float2 w1; w1.x = v2; w1.y = v3;
                *(float2*)&outf[(size_t)m * DD + n] = w0;
                *(float2*)&outf[(size_t)(m + 8) * DD + n] = w1;
            }
        }
    }
#undef LDTILE
#undef STTILE
}

// ============================================================
// Flash attention, fp16 HMMA m16n8k16. BQ=128, BK=64, dh=64.
// 128 thr = 4 warps; warp w owns q rows [w*32, w*32+32).
// Q frags hoisted to regs (ldmatrix once); P passed S-regs -> PV
// operands directly (no smem round trip). V via ldmatrix.trans.
// smem: Qs[128][72]h, Ks[64][72]h, Vs[64][72]h  (36864 B static)
// ============================================================
#define FSTR 72
__global__ __launch_bounds__(128)
void flash_h()
{
    __shared__ __align__(16) __half fsm[(128 + 64 + 64) * FSTR];
    __half* Qs = fsm;
    __half* Ks = fsm + 128 * FSTR;
    __half* Vs = Ks + 64 * FSTR;
    const uint32_t sqb = smem_u32(Qs);
    const uint32_t skb = smem_u32(Ks);
    const uint32_t svb = smem_u32(Vs);

    const int tid  = threadIdx.x;
    const int lane = tid & 31, warp = tid >> 5;
    const int g = lane >> 2, tig = lane & 3;
    const int q0 = blockIdx.x * 128;
    const int bh = blockIdx.y;
    const int qbase = warp * 32;

    const int l15 = lane & 15, hi8 = (lane >> 4) * 8;
    const int bl = (lane & 7) + (lane >> 4) * 8;          // K n-row map
    const int bk = ((lane >> 3) & 1) * 8;                 // K k-half
    const int vr = (lane & 7) + ((lane >> 3) & 1) * 8;    // V key-row map (trans)
    const int vc = (lane >> 4) * 8;                       // V d-half

    const __half* qb = g_q + (size_t)bh * TT * DH;
    const __half* kb = g_k + (size_t)bh * TT * DH;
    const __half* vb = g_v + (size_t)bh * TT * DH;

    // stage Q (scale by 1/8 — exact in fp16)
    const __half2 hs = __floats2half2_rn(0.125f, 0.125f);
#pragma unroll
    for (int it = 0; it < 8; it++) {
        const int i = tid + it * 128;
        const int r = i >> 3, c8 = (i & 7) * 8;
        uint4 v = *(const uint4*)&qb[(size_t)(q0 + r) * DH + c8];
        __half2* hv = (__half2*)&v;
#pragma unroll
        for (int j = 0; j < 4; j++) hv[j] = __hmul2(hv[j], hs);
        *(uint4*)&Qs[r * FSTR + c8] = v;
    }
    __syncthreads();

    // hoist Q fragments (per warp: 4 k-steps x 2 mi)
    uint32_t qf[4][2][4];
#pragma unroll
    for (int kk = 0; kk < 4; kk++)
#pragma unroll
        for (int mi = 0; mi < 2; mi++) {
            const int row = qbase + mi * 16 + l15;
            LDM_X4(qf[kk][mi], sqb + (uint32_t)(row * FSTR + kk * 16 + hi8) * 2);
        }

    float o[2][8][4];
    float mr[2][2], lr[2][2];
#pragma unroll
    for (int mi = 0; mi < 2; mi++) {
        mr[mi][0] = mr[mi][1] = -1e30f;
        lr[mi][0] = lr[mi][1] = 0.f;
#pragma unroll
        for (int j = 0; j < 8; j++)
#pragma unroll
            for (int k = 0; k < 4; k++) o[mi][j][k] = 0.f;
    }

    const int nkt = (q0 >> 6) + 2;
    for (int kt = 0; kt < nkt; kt++) {
        const int k0 = kt * 64;
        __syncthreads();
#pragma unroll
        for (int it = 0; it < 4; it++) {
            const int i = tid + it * 128;
            const int r = i >> 3, c8 = (i & 7) * 8;
            *(uint4*)&Ks[r * FSTR + c8] = *(const uint4*)&kb[(size_t)(k0 + r) * DH + c8];
            *(uint4*)&Vs[r * FSTR + c8] = *(const uint4*)&vb[(size_t)(k0 + r) * DH + c8];
        }
        __syncthreads();

        if (k0 > q0 + qbase + 31) continue;   // warp fully masked

        // ---- S = Q K^T (warp 32x64) ----
        float s[2][8][4];
#pragma unroll
        for (int mi = 0; mi < 2; mi++)
#pragma unroll
            for (int i = 0; i < 8; i++)
#pragma unroll
                for (int j = 0; j < 4; j++) s[mi][i][j] = 0.f;

#pragma unroll
        for (int kk = 0; kk < 4; kk++) {
            uint32_t kf[8][2];
#pragma unroll
            for (int njp = 0; njp < 4; njp++) {
                uint32_t t[4];
                const int row = njp * 16 + bl;
                LDM_X4(t, skb + (uint32_t)(row * FSTR + kk * 16 + bk) * 2);
                kf[2 * njp][0] = t[0]; kf[2 * njp][1] = t[1];
                kf[2 * njp + 1][0] = t[2]; kf[2 * njp + 1][1] = t[3];
            }
#pragma unroll
            for (int mi = 0; mi < 2; mi++)
#pragma unroll
                for (int ni = 0; ni < 8; ni++)
                    mma_f16(s[mi][ni], qf[kk][mi][0], qf[kk][mi][1],
                            qf[kk][mi][2], qf[kk][mi][3], kf[ni][0], kf[ni][1]);
        }

        // ---- causal mask ----
#pragma unroll
        for (int mi = 0; mi < 2; mi++) {
            if (k0 + 63 > q0 + qbase + mi * 16) {
                const int qr0 = q0 + qbase + mi * 16 + g, qr1 = qr0 + 8;
#pragma unroll
                for (int ni = 0; ni < 8; ni++) {
                    const int key0 = k0 + ni * 8 + 2 * tig;
                    if (key0 > qr0)     s[mi][ni][0] = -1e30f;
                    if (key0 + 1 > qr0) s[mi][ni][1] = -1e30f;
                    if (key0 > qr1)     s[mi][ni][2] = -1e30f;
                    if (key0 + 1 > qr1) s[mi][ni][3] = -1e30f;
                }
            }
        }

        // ---- online softmax (p overwrites s) ----
#pragma unroll
        for (int mi = 0; mi < 2; mi++) {
            float rm0 = -1e30f, rm1 = -1e30f;
#pragma unroll
            for (int ni = 0; ni < 8; ni++) {
                rm0 = fmaxf(rm0, fmaxf(s[mi][ni][0], s[mi][ni][1]));
                rm1 = fmaxf(rm1, fmaxf(s[mi][ni][2], s[mi][ni][3]));
            }
            rm0 = fmaxf(rm0, __shfl_xor_sync(0xffffffffu, rm0, 1));
            rm0 = fmaxf(rm0, __shfl_xor_sync(0xffffffffu, rm0, 2));
            rm1 = fmaxf(rm1, __shfl_xor_sync(0xffffffffu, rm1, 1));
            rm1 = fmaxf(rm1, __shfl_xor_sync(0xffffffffu, rm1, 2));

            const float mn0 = fmaxf(mr[mi][0], rm0), mn1 = fmaxf(mr[mi][1], rm1);
            const float c0 = __expf(mr[mi][0] - mn0), c1 = __expf(mr[mi][1] - mn1);
            mr[mi][0] = mn0; mr[mi][1] = mn1;
            lr[mi][0] *= c0; lr[mi][1] *= c1;
#pragma unroll
            for (int nj = 0; nj < 8; nj++) {
                o[mi][nj][0] *= c0; o[mi][nj][1] *= c0;
                o[mi][nj][2] *= c1; o[mi][nj][3] *= c1;
            }

            float rs0 = 0.f, rs1 = 0.f;
#pragma unroll
            for (int ni = 0; ni < 8; ni++) {
                s[mi][ni][0] = __expf(s[mi][ni][0] - mn0);
                s[mi][ni][1] = __expf(s[mi][ni][1] - mn0);
                s[mi][ni][2] = __expf(s[mi][ni][2] - mn1);
                s[mi][ni][3] = __expf(s[mi][ni][3] - mn1);
                rs0 += s[mi][ni][0] + s[mi][ni][1];
                rs1 += s[mi][ni][2] + s[mi][ni][3];
            }
            rs0 += __shfl_xor_sync(0xffffffffu, rs0, 1);
            rs0 += __shfl_xor_sync(0xffffffffu, rs0, 2);
            rs1 += __shfl_xor_sync(0xffffffffu, rs1, 1);
            rs1 += __shfl_xor_sync(0xffffffffu, rs1, 2);
            lr[mi][0] += rs0; lr[mi][1] += rs1;
        }

        // ---- O += P V (P from S-regs, V via ldmatrix.trans) ----
#pragma unroll
        for (int kk2 = 0; kk2 < 4; kk2++) {
            uint32_t vf[8][2];
#pragma unroll
            for (int njp = 0; njp < 4; njp++) {
                uint32_t t[4];
                const int row = kk2 * 16 + vr;
                LDM_X4T(t, svb + (uint32_t)(row * FSTR + njp * 16 + vc) * 2);
                vf[2 * njp][0] = t[0]; vf[2 * njp][1] = t[1];
                vf[2 * njp + 1][0] = t[2]; vf[2 * njp + 1][1] = t[3];
            }
#pragma unroll
            for (int mi = 0; mi < 2; mi++) {
                const uint32_t a0 = f22u(s[mi][2 * kk2][0], s[mi][2 * kk2][1]);
                const uint32_t a1 = f22u(s[mi][2 * kk2][2], s[mi][2 * kk2][3]);
                const uint32_t a2 = f22u(s[mi][2 * kk2 + 1][0], s[mi][2 * kk2 + 1][1]);
                const uint32_t a3 = f22u(s[mi][2 * kk2 + 1][2], s[mi][2 * kk2 + 1][3]);
#pragma unroll
                for (int nj = 0; nj < 8; nj++)
                    mma_f16(o[mi][nj], a0, a1, a2, a3, vf[nj][0], vf[nj][1]);
            }
        }
    }

    // epilogue: normalize, store half to g_att[b][t][h*64+d]
    const int b = bh >> 4, h = bh & 15;
#pragma unroll
    for (int mi = 0; mi < 2; mi++) {
        const float inv0 = 1.f / lr[mi][0], inv1 = 1.f / lr[mi][1];
        const int t0 = q0 + qbase + mi * 16 + g;
#pragma unroll
        for (int nj = 0; nj < 8; nj++) {
            const size_t base = ((size_t)b * TT + t0) * DD + h * DH + nj * 8 + 2 * tig;
            *(__half2*)&g_att[base] = __floats2half2_rn(o[mi][nj][0] * inv0,
                                                        o[mi][nj][1] * inv0);
            *(__half2*)&g_att[base + (size_t)8 * DD] =
                __floats2half2_rn(o[mi][nj][2] * inv1, o[mi][nj][3] * inv1);
        }
    }
}

// ============================================================
extern "C" void kernel_launch(void* const* d_in, const int* in_sizes, int n_in,
                              void* d_out, int out_size)
{
    const float* x     = (const float*)d_in[0];
    const float* W_qkv = (const float*)d_in[1];
    const float* b_qkv = (const float*)d_in[2];
    const float* W_out = (const float*)d_in[3];
    const float* b_out = (const float*)d_in[4];
    float* out = (float*)d_out;

    const int gemm_smem = 2 * GBUFB;   // 61440

    static int attr_set = 0;
    if (!attr_set) {
        cudaFuncSetAttribute(h_gemm<0>,
                             cudaFuncAttributeMaxDynamicSharedMemorySize, gemm_smem);
        cudaFuncSetAttribute(h_gemm<1>,
                             cudaFuncAttributeMaxDynamicSharedMemorySize, gemm_smem);
        attr_set = 1;
    }

    __half* wqkvT; cudaGetSymbolAddress((void**)&wqkvT, g_wqkvT);
    __half* woutT; cudaGetSymbolAddress((void**)&woutT, g_woutT);
    __half* attp;  cudaGetSymbolAddress((void**)&attp,  g_att);

    // 0) weight transposes + half conversion
    transpose_cvt<<<dim3(3 * DD / 32, DD / 32), dim3(32, 8)>>>(W_qkv, wqkvT, DD, 3 * DD);
    transpose_cvt<<<dim3(DD / 32, DD / 32), dim3(32, 8)>>>(W_out, woutT, DD, DD);

    // 1) QKV projection (fp16 HMMA) + head-split scatter
    dim3 g1(3 * DD / 256, MROWS / 128);   // 12 x 64
    h_gemm<0><<<g1, 256, gemm_smem>>>(x, nullptr, wqkvT, b_qkv, nullptr);

    // 2) causal flash attention (fp16 HMMA)
    dim3 g2(TT / 128, BB * HH);           // 16 x 64
    flash_h<<<g2, 128>>>();

    // 3) output projection (fp16 HMMA)
    dim3 g3(DD / 256, MROWS / 128);       // 4 x 64
    h_gemm<1><<<g3, 256, gemm_smem>>>(nullptr, attp, woutT, b_out, out);
}